// round 1
// baseline (speedup 1.0000x reference)
#include <cuda_runtime.h>

#define DMODEL 1024
#define NHEAD  16
#define DHEAD  64
#define BATCH  4
#define SEQ    2048
#define MTOT   (BATCH * SEQ)          // 8192

// Scratch (device globals; no allocation allowed)
__device__ float g_q[BATCH * NHEAD * SEQ * DHEAD];   // [b,h,n,d], pre-scaled
__device__ float g_k[BATCH * NHEAD * SEQ * DHEAD];
__device__ float g_v[BATCH * NHEAD * SEQ * DHEAD];
__device__ float g_o[MTOT * DMODEL];                 // [b,n, h*d]

// ---------------------------------------------------------------------------
// GEMM1: qkv = x @ w_qkv + b_qkv, scattered into g_q/g_k/g_v as [b,h,n,d].
// Tiles: BM=64, BN=64, BK=16; 256 threads; 4x4 microtile per thread.
// ---------------------------------------------------------------------------
__global__ __launch_bounds__(256) void qkv_gemm(const float* __restrict__ X,
                                                const float* __restrict__ W,
                                                const float* __restrict__ bias) {
    __shared__ float As[64][17];   // padded: compute reads As[m][k]
    __shared__ float Bs[16][64];

    const int n0 = blockIdx.x * 64;
    const int m0 = blockIdx.y * 64;
    const int t  = threadIdx.x;
    const int tx = t & 15;
    const int ty = t >> 4;

    float acc[4][4];
#pragma unroll
    for (int i = 0; i < 4; i++)
#pragma unroll
        for (int j = 0; j < 4; j++) acc[i][j] = 0.f;

    for (int k0 = 0; k0 < DMODEL; k0 += 16) {
        // load A tile 64x16 (4 threads per row, float4 each)
        {
            int r = t >> 2;
            int c = (t & 3) << 2;
            float4 xa = *(const float4*)&X[(size_t)(m0 + r) * DMODEL + k0 + c];
            As[r][c + 0] = xa.x; As[r][c + 1] = xa.y;
            As[r][c + 2] = xa.z; As[r][c + 3] = xa.w;
        }
        // load B tile 16x64 (one float4 per thread)
        {
            int br = t >> 4;
            int bc = (t & 15) << 2;
            *(float4*)&Bs[br][bc] =
                *(const float4*)&W[(size_t)(k0 + br) * (3 * DMODEL) + n0 + bc];
        }
        __syncthreads();
#pragma unroll
        for (int kk = 0; kk < 16; kk++) {
            float a0 = As[ty * 4 + 0][kk];
            float a1 = As[ty * 4 + 1][kk];
            float a2 = As[ty * 4 + 2][kk];
            float a3 = As[ty * 4 + 3][kk];
            float4 b4 = *(const float4*)&Bs[kk][tx * 4];
            acc[0][0] += a0 * b4.x; acc[0][1] += a0 * b4.y; acc[0][2] += a0 * b4.z; acc[0][3] += a0 * b4.w;
            acc[1][0] += a1 * b4.x; acc[1][1] += a1 * b4.y; acc[1][2] += a1 * b4.z; acc[1][3] += a1 * b4.w;
            acc[2][0] += a2 * b4.x; acc[2][1] += a2 * b4.y; acc[2][2] += a2 * b4.z; acc[2][3] += a2 * b4.w;
            acc[3][0] += a3 * b4.x; acc[3][1] += a3 * b4.y; acc[3][2] += a3 * b4.z; acc[3][3] += a3 * b4.w;
        }
        __syncthreads();
    }

    // epilogue: bias + scatter to [b,h,n,d]; fold softmax scale into q
#pragma unroll
    for (int i = 0; i < 4; i++) {
        int m  = m0 + ty * 4 + i;
        int bi = m >> 11;          // /SEQ
        int ni = m & (SEQ - 1);
#pragma unroll
        for (int j = 0; j < 4; j++) {
            int c = n0 + tx * 4 + j;
            float v = acc[i][j] + bias[c];
            int which = c >> 10;       // 0=q,1=k,2=v
            int rem   = c & 1023;
            int h     = rem >> 6;
            int dd    = rem & 63;
            int idx   = (((bi * NHEAD + h) * SEQ) + ni) * DHEAD + dd;
            if (which == 0)      g_q[idx] = v * 0.125f;   // 64^-0.5
            else if (which == 1) g_k[idx] = v;
            else                 g_v[idx] = v;
        }
    }
}

// ---------------------------------------------------------------------------
// Flash attention (causal). One thread = one query row. K/V streamed through
// SMEM in 16-row tiles; online softmax; o accumulated in registers.
// Grid: (SEQ/128, BATCH*NHEAD), block 128.
// ---------------------------------------------------------------------------
__global__ __launch_bounds__(128) void attn_kernel() {
    const int bh = blockIdx.y;                 // b*16 + h
    const int qb = blockIdx.x;
    const int t  = threadIdx.x;
    const int qi = qb * 128 + t;

    __shared__ float Ks[16][64];
    __shared__ float Vs[16][64];

    const float* Qrow = g_q + ((size_t)bh * SEQ + qi) * DHEAD;
    float q[64];
#pragma unroll
    for (int k = 0; k < 64; k += 4) {
        float4 v4 = *(const float4*)&Qrow[k];
        q[k] = v4.x; q[k + 1] = v4.y; q[k + 2] = v4.z; q[k + 3] = v4.w;
    }

    float o[64];
#pragma unroll
    for (int d = 0; d < 64; d++) o[d] = 0.f;
    float m_run = -1e30f, l_run = 0.f;

    const int kend = qb * 128 + 128;           // causal bound for this block
    for (int ks = 0; ks < kend; ks += 16) {
        const float4* Kb = (const float4*)(g_k + ((size_t)bh * SEQ + ks) * DHEAD);
        const float4* Vb = (const float4*)(g_v + ((size_t)bh * SEQ + ks) * DHEAD);
        __syncthreads();
#pragma unroll
        for (int i = 0; i < 2; i++) {
            int idx = t + i * 128;             // 256 float4 per tile
            ((float4*)Ks)[idx] = Kb[idx];
            ((float4*)Vs)[idx] = Vb[idx];
        }
        __syncthreads();

        float s[16];
#pragma unroll
        for (int j = 0; j < 16; j++) {
            const float4* kr = (const float4*)&Ks[j][0];
            float a = 0.f;
#pragma unroll
            for (int k4 = 0; k4 < 16; k4++) {
                float4 kv = kr[k4];
                a += q[4 * k4 + 0] * kv.x + q[4 * k4 + 1] * kv.y
                   + q[4 * k4 + 2] * kv.z + q[4 * k4 + 3] * kv.w;
            }
            s[j] = (ks + j <= qi) ? a : -1e30f;
        }

        float mnew = m_run;
#pragma unroll
        for (int j = 0; j < 16; j++) mnew = fmaxf(mnew, s[j]);
        float alpha = __expf(m_run - mnew);
        float p[16];
        float psum = 0.f;
#pragma unroll
        for (int j = 0; j < 16; j++) { p[j] = __expf(s[j] - mnew); psum += p[j]; }
        l_run = l_run * alpha + psum;
        m_run = mnew;

#pragma unroll
        for (int d = 0; d < 64; d++) o[d] *= alpha;
#pragma unroll
        for (int j = 0; j < 16; j++) {
            float pj = p[j];
            const float4* vr = (const float4*)&Vs[j][0];
#pragma unroll
            for (int d4 = 0; d4 < 16; d4++) {
                float4 vv = vr[d4];
                o[4 * d4 + 0] += pj * vv.x;
                o[4 * d4 + 1] += pj * vv.y;
                o[4 * d4 + 2] += pj * vv.z;
                o[4 * d4 + 3] += pj * vv.w;
            }
        }
    }

    float inv = 1.f / l_run;
    const int bi = bh >> 4;
    const int h  = bh & 15;
    float* Ob = g_o + ((size_t)(bi * SEQ + qi)) * DMODEL + h * DHEAD;
#pragma unroll
    for (int d = 0; d < 64; d += 4) {
        float4 v4;
        v4.x = o[d] * inv; v4.y = o[d + 1] * inv;
        v4.z = o[d + 2] * inv; v4.w = o[d + 3] * inv;
        *(float4*)&Ob[d] = v4;
    }
}

// ---------------------------------------------------------------------------
// GEMM2: out = g_o @ w_out + b_out
// ---------------------------------------------------------------------------
__global__ __launch_bounds__(256) void out_gemm(const float* __restrict__ W,
                                                const float* __restrict__ bias,
                                                float* __restrict__ out) {
    __shared__ float As[64][17];
    __shared__ float Bs[16][64];

    const int n0 = blockIdx.x * 64;
    const int m0 = blockIdx.y * 64;
    const int t  = threadIdx.x;
    const int tx = t & 15;
    const int ty = t >> 4;

    float acc[4][4];
#pragma unroll
    for (int i = 0; i < 4; i++)
#pragma unroll
        for (int j = 0; j < 4; j++) acc[i][j] = 0.f;

    for (int k0 = 0; k0 < DMODEL; k0 += 16) {
        {
            int r = t >> 2;
            int c = (t & 3) << 2;
            float4 xa = *(const float4*)&g_o[(size_t)(m0 + r) * DMODEL + k0 + c];
            As[r][c + 0] = xa.x; As[r][c + 1] = xa.y;
            As[r][c + 2] = xa.z; As[r][c + 3] = xa.w;
        }
        {
            int br = t >> 4;
            int bc = (t & 15) << 2;
            *(float4*)&Bs[br][bc] =
                *(const float4*)&W[(size_t)(k0 + br) * DMODEL + n0 + bc];
        }
        __syncthreads();
#pragma unroll
        for (int kk = 0; kk < 16; kk++) {
            float a0 = As[ty * 4 + 0][kk];
            float a1 = As[ty * 4 + 1][kk];
            float a2 = As[ty * 4 + 2][kk];
            float a3 = As[ty * 4 + 3][kk];
            float4 b4 = *(const float4*)&Bs[kk][tx * 4];
            acc[0][0] += a0 * b4.x; acc[0][1] += a0 * b4.y; acc[0][2] += a0 * b4.z; acc[0][3] += a0 * b4.w;
            acc[1][0] += a1 * b4.x; acc[1][1] += a1 * b4.y; acc[1][2] += a1 * b4.z; acc[1][3] += a1 * b4.w;
            acc[2][0] += a2 * b4.x; acc[2][1] += a2 * b4.y; acc[2][2] += a2 * b4.z; acc[2][3] += a2 * b4.w;
            acc[3][0] += a3 * b4.x; acc[3][1] += a3 * b4.y; acc[3][2] += a3 * b4.z; acc[3][3] += a3 * b4.w;
        }
        __syncthreads();
    }

#pragma unroll
    for (int i = 0; i < 4; i++) {
        int m = m0 + ty * 4 + i;
#pragma unroll
        for (int j = 0; j < 4; j++) {
            int c = n0 + tx * 4 + j;
            out[(size_t)m * DMODEL + c] = acc[i][j] + bias[c];
        }
    }
}

extern "C" void kernel_launch(void* const* d_in, const int* in_sizes, int n_in,
                              void* d_out, int out_size) {
    const float* x     = (const float*)d_in[0];
    const float* w_qkv = (const float*)d_in[1];
    const float* b_qkv = (const float*)d_in[2];
    const float* w_out = (const float*)d_in[3];
    const float* b_out = (const float*)d_in[4];
    float* out = (float*)d_out;

    dim3 g1(3 * DMODEL / 64, MTOT / 64);   // 48 x 128
    qkv_gemm<<<g1, 256>>>(x, w_qkv, b_qkv);

    attn_kernel<<<dim3(SEQ / 128, BATCH * NHEAD), 128>>>();

    dim3 g2(DMODEL / 64, MTOT / 64);       // 16 x 128
    out_gemm<<<g2, 256>>>(w_out, b_out, out);
}

// round 7
// speedup vs baseline: 1.0038x; 1.0038x over previous
#include <cuda_runtime.h>
#include <cuda_bf16.h>
#include <cstdint>

#define DMODEL 1024
#define NHEAD  16
#define DHEAD  64
#define BATCH  4
#define SEQ    2048
#define MTOT   (BATCH * SEQ)          // 8192

#define BK 32
#define KS 40                          // padded smem row stride (bf16 elems)

// Scratch (device globals; no allocation allowed)
__device__ float g_q[BATCH * NHEAD * SEQ * DHEAD];   // [b,h,n,d], q pre-scaled
__device__ float g_k[BATCH * NHEAD * SEQ * DHEAD];
__device__ float g_v[BATCH * NHEAD * SEQ * DHEAD];
__device__ float g_o[MTOT * DMODEL];                 // [b,n, h*d]

// ---------------------------------------------------------------------------
// helpers
// ---------------------------------------------------------------------------
__device__ __forceinline__ uint32_t smem_u32(const void* p) {
    uint32_t a;
    asm("{ .reg .u64 t; cvta.to.shared.u64 t, %1; cvt.u32.u64 %0, t; }"
        : "=r"(a) : "l"(p));
    return a;
}

__device__ __forceinline__ void ldsm_x4(uint32_t* r, uint32_t addr) {
    asm volatile("ldmatrix.sync.aligned.m8n8.x4.shared.b16 {%0,%1,%2,%3}, [%4];"
                 : "=r"(r[0]), "=r"(r[1]), "=r"(r[2]), "=r"(r[3]) : "r"(addr));
}

__device__ __forceinline__ void mma_bf16(float* d, const uint32_t* a,
                                         uint32_t b0, uint32_t b1) {
    asm volatile(
        "mma.sync.aligned.m16n8k16.row.col.f32.bf16.bf16.f32 "
        "{%0,%1,%2,%3}, {%4,%5,%6,%7}, {%8,%9}, {%0,%1,%2,%3};"
        : "+f"(d[0]), "+f"(d[1]), "+f"(d[2]), "+f"(d[3])
        : "r"(a[0]), "r"(a[1]), "r"(a[2]), "r"(a[3]), "r"(b0), "r"(b1));
}

// Split two floats into packed bf16x2 hi and lo
__device__ __forceinline__ void split2(float a, float b, uint32_t& h, uint32_t& l) {
    __nv_bfloat162 hh;
    hh.x = __float2bfloat16(a);
    hh.y = __float2bfloat16(b);
    float la = a - __bfloat162float(hh.x);
    float lb = b - __bfloat162float(hh.y);
    __nv_bfloat162 ll;
    ll.x = __float2bfloat16(la);
    ll.y = __float2bfloat16(lb);
    h = *(uint32_t*)&hh;
    l = *(uint32_t*)&ll;
}

// ---------------------------------------------------------------------------
// HMMA GEMM: C[M,N] = A[M,1024] @ W[1024,Ntot] + bias, 2-term bf16 split
// (hh + hl + lh). CTA 128x128, K-chunk 32, 256 threads (8 warps, 4M x 2N),
// warp tile 32x64 via mma.m16n8k16.
// SCATTER=1: A = x, scatter into g_q/g_k/g_v (q * 0.125).
// SCATTER=0: A = g_o, out = result.
// ---------------------------------------------------------------------------
template <int SCATTER>
__global__ __launch_bounds__(256) void gemm_mma(const float* __restrict__ A,
                                                const float* __restrict__ W,
                                                const float* __restrict__ bias,
                                                float* __restrict__ out,
                                                int Ntot) {
    __shared__ __nv_bfloat16 Ah_s[128 * KS];
    __shared__ __nv_bfloat16 Al_s[128 * KS];
    __shared__ __nv_bfloat16 Bh_s[128 * KS];
    __shared__ __nv_bfloat16 Bl_s[128 * KS];

    const int tid  = threadIdx.x;
    const int warp = tid >> 5;
    const int lane = tid & 31;
    const int wm   = warp & 3;         // 0..3 -> M groups of 32
    const int wn   = warp >> 2;        // 0..1 -> N groups of 64
    const int n0   = blockIdx.x * 128;
    const int m0   = blockIdx.y * 128;

    const float* Abase = SCATTER ? A : g_o;

    float acc[2][8][4];
#pragma unroll
    for (int i = 0; i < 2; i++)
#pragma unroll
        for (int j = 0; j < 8; j++)
#pragma unroll
            for (int r = 0; r < 4; r++) acc[i][j][r] = 0.f;

    // ldmatrix source addresses (fixed per thread; column offset varies by kstep)
    const uint32_t sAh = smem_u32(Ah_s);
    const uint32_t sAl = smem_u32(Al_s);
    const uint32_t sBh = smem_u32(Bh_s);
    const uint32_t sBl = smem_u32(Bl_s);
    const int lrow  = lane & 15;
    const int lcol8 = (lane >> 4) * 8;

    for (int k0 = 0; k0 < DMODEL; k0 += BK) {
        __syncthreads();
        // ---- load A tile 128x32 fp32 -> bf16 hi/lo ----
#pragma unroll
        for (int it = 0; it < 4; it++) {
            int idx = it * 256 + tid;          // 1024 float4
            int row = idx >> 3;
            int c4  = (idx & 7) * 4;
            float4 v = *(const float4*)&Abase[(size_t)(m0 + row) * DMODEL + k0 + c4];
            uint32_t h01, l01, h23, l23;
            split2(v.x, v.y, h01, l01);
            split2(v.z, v.w, h23, l23);
            int off = row * KS + c4;
            *(uint32_t*)&Ah_s[off]     = h01;
            *(uint32_t*)&Ah_s[off + 2] = h23;
            *(uint32_t*)&Al_s[off]     = l01;
            *(uint32_t*)&Al_s[off + 2] = l23;
        }
        // ---- load B tile 32x128 fp32, transpose to Bs[n][k], bf16 hi/lo ----
#pragma unroll
        for (int it = 0; it < 4; it++) {
            int idx = it * 256 + tid;          // 1024 float4
            int k   = idx >> 5;
            int n4  = (idx & 31) * 4;
            float4 v = *(const float4*)&W[(size_t)(k0 + k) * Ntot + n0 + n4];
            float vv[4] = {v.x, v.y, v.z, v.w};
#pragma unroll
            for (int j = 0; j < 4; j++) {
                __nv_bfloat16 h = __float2bfloat16(vv[j]);
                __nv_bfloat16 l = __float2bfloat16(vv[j] - __bfloat162float(h));
                Bh_s[(n4 + j) * KS + k] = h;
                Bl_s[(n4 + j) * KS + k] = l;
            }
        }
        __syncthreads();

        // ---- compute: 2 k16 steps, combos hh / lh / hl ----
#pragma unroll
        for (int ks = 0; ks < 2; ks++) {
            const int kk = ks * 16 + lcol8;
            uint32_t a_hi[2][4], a_lo[2][4], b_cur[4][4];
#pragma unroll
            for (int mf = 0; mf < 2; mf++) {
                int r = wm * 32 + mf * 16 + lrow;
                ldsm_x4(a_hi[mf], sAh + (uint32_t)(r * KS + kk) * 2);
                ldsm_x4(a_lo[mf], sAl + (uint32_t)(r * KS + kk) * 2);
            }
#pragma unroll
            for (int g = 0; g < 4; g++) {
                int r = wn * 64 + g * 16 + lrow;
                ldsm_x4(b_cur[g], sBh + (uint32_t)(r * KS + kk) * 2);
            }
            // hh + lh (B = hi)
#pragma unroll
            for (int mf = 0; mf < 2; mf++)
#pragma unroll
                for (int j = 0; j < 8; j++) {
                    int g = j >> 1, w = j & 1;
                    mma_bf16(acc[mf][j], a_hi[mf], b_cur[g][w], b_cur[g][w + 2]);
                    mma_bf16(acc[mf][j], a_lo[mf], b_cur[g][w], b_cur[g][w + 2]);
                }
            // hl (B = lo)
#pragma unroll
            for (int g = 0; g < 4; g++) {
                int r = wn * 64 + g * 16 + lrow;
                ldsm_x4(b_cur[g], sBl + (uint32_t)(r * KS + kk) * 2);
            }
#pragma unroll
            for (int mf = 0; mf < 2; mf++)
#pragma unroll
                for (int j = 0; j < 8; j++) {
                    int g = j >> 1, w = j & 1;
                    mma_bf16(acc[mf][j], a_hi[mf], b_cur[g][w], b_cur[g][w + 2]);
                }
        }
    }

    // ---- epilogue ----
    const int gid = lane >> 2;    // row within m16 frag (and +8)
    const int tig = lane & 3;     // col pair
#pragma unroll
    for (int mf = 0; mf < 2; mf++) {
#pragma unroll
        for (int j = 0; j < 8; j++) {
#pragma unroll
            for (int r = 0; r < 4; r++) {
                int m   = m0 + wm * 32 + mf * 16 + gid + ((r >> 1) * 8);
                int col = n0 + wn * 64 + j * 8 + tig * 2 + (r & 1);
                float v = acc[mf][j][r] + bias[col];
                if (SCATTER) {
                    int bi = m >> 11;
                    int ni = m & (SEQ - 1);
                    int which = col >> 10;
                    int rem   = col & 1023;
                    int h     = rem >> 6;
                    int dd    = rem & 63;
                    size_t idx = ((((size_t)bi * NHEAD + h) * SEQ) + ni) * DHEAD + dd;
                    if (which == 0)      g_q[idx] = v * 0.125f;
                    else if (which == 1) g_k[idx] = v;
                    else                 g_v[idx] = v;
                } else {
                    out[(size_t)m * DMODEL + col] = v;
                }
            }
        }
    }
}

// ---------------------------------------------------------------------------
// Flash attention (causal). One thread = one query row. (unchanged from R1)
// ---------------------------------------------------------------------------
__global__ __launch_bounds__(128) void attn_kernel() {
    const int bh = blockIdx.y;
    const int qb = blockIdx.x;
    const int t  = threadIdx.x;
    const int qi = qb * 128 + t;

    __shared__ float Ks[16][64];
    __shared__ float Vs[16][64];

    const float* Qrow = g_q + ((size_t)bh * SEQ + qi) * DHEAD;
    float q[64];
#pragma unroll
    for (int k = 0; k < 64; k += 4) {
        float4 v4 = *(const float4*)&Qrow[k];
        q[k] = v4.x; q[k + 1] = v4.y; q[k + 2] = v4.z; q[k + 3] = v4.w;
    }

    float o[64];
#pragma unroll
    for (int d = 0; d < 64; d++) o[d] = 0.f;
    float m_run = -1e30f, l_run = 0.f;

    const int kend = qb * 128 + 128;
    for (int ks = 0; ks < kend; ks += 16) {
        const float4* Kb = (const float4*)(g_k + ((size_t)bh * SEQ + ks) * DHEAD);
        const float4* Vb = (const float4*)(g_v + ((size_t)bh * SEQ + ks) * DHEAD);
        __syncthreads();
#pragma unroll
        for (int i = 0; i < 2; i++) {
            int idx = t + i * 128;
            ((float4*)Ks)[idx] = Kb[idx];
            ((float4*)Vs)[idx] = Vb[idx];
        }
        __syncthreads();

        float s[16];
#pragma unroll
        for (int j = 0; j < 16; j++) {
            const float4* kr = (const float4*)&Ks[j][0];
            float a = 0.f;
#pragma unroll
            for (int k4 = 0; k4 < 16; k4++) {
                float4 kv = kr[k4];
                a += q[4 * k4 + 0] * kv.x + q[4 * k4 + 1] * kv.y
                   + q[4 * k4 + 2] * kv.z + q[4 * k4 + 3] * kv.w;
            }
            s[j] = (ks + j <= qi) ? a : -1e30f;
        }

        float mnew = m_run;
#pragma unroll
        for (int j = 0; j < 16; j++) mnew = fmaxf(mnew, s[j]);
        float alpha = __expf(m_run - mnew);
        float p[16];
        float psum = 0.f;
#pragma unroll
        for (int j = 0; j < 16; j++) { p[j] = __expf(s[j] - mnew); psum += p[j]; }
        l_run = l_run * alpha + psum;
        m_run = mnew;

#pragma unroll
        for (int d = 0; d < 64; d++) o[d] *= alpha;
#pragma unroll
        for (int j = 0; j < 16; j++) {
            float pj = p[j];
            const float4* vr = (const float4*)&Vs[j][0];
#pragma unroll
            for (int d4 = 0; d4 < 16; d4++) {
                float4 vv = vr[d4];
                o[4 * d4 + 0] += pj * vv.x;
                o[4 * d4 + 1] += pj * vv.y;
                o[4 * d4 + 2] += pj * vv.z;
                o[4 * d4 + 3] += pj * vv.w;
            }
        }
    }

    float inv = 1.f / l_run;
    const int bi = bh >> 4;
    const int h  = bh & 15;
    float* Ob = g_o + ((size_t)(bi * SEQ + qi)) * DMODEL + h * DHEAD;
#pragma unroll
    for (int d = 0; d < 64; d += 4) {
        float4 v4;
        v4.x = o[d] * inv; v4.y = o[d + 1] * inv;
        v4.z = o[d + 2] * inv; v4.w = o[d + 3] * inv;
        *(float4*)&Ob[d] = v4;
    }
}

extern "C" void kernel_launch(void* const* d_in, const int* in_sizes, int n_in,
                              void* d_out, int out_size) {
    const float* x     = (const float*)d_in[0];
    const float* w_qkv = (const float*)d_in[1];
    const float* b_qkv = (const float*)d_in[2];
    const float* w_out = (const float*)d_in[3];
    const float* b_out = (const float*)d_in[4];
    float* out = (float*)d_out;

    // qkv = x @ w_qkv + b_qkv  -> scatter to g_q/g_k/g_v
    gemm_mma<1><<<dim3(3 * DMODEL / 128, MTOT / 128), 256>>>(
        x, w_qkv, b_qkv, nullptr, 3 * DMODEL);

    attn_kernel<<<dim3(SEQ / 128, BATCH * NHEAD), 128>>>();

    // out = g_o @ w_out + b_out
    gemm_mma<0><<<dim3(DMODEL / 128, MTOT / 128), 256>>>(
        nullptr, w_out, b_out, out, DMODEL);
}

// round 10
// speedup vs baseline: 2.4511x; 2.4418x over previous
#include <cuda_runtime.h>
#include <cuda_bf16.h>
#include <cstdint>

#define DMODEL 1024
#define NHEAD  16
#define DHEAD  64
#define BATCH  4
#define SEQ    2048
#define MTOT   (BATCH * SEQ)          // 8192
#define BH     (BATCH * NHEAD)        // 64

// ---------------------------------------------------------------------------
// Device-global scratch (no allocation allowed)
// ---------------------------------------------------------------------------
__device__ float g_o[MTOT * DMODEL];                 // attention output [b,n,h*d]

// bf16 hi/lo operands for GEMMs
__device__ __nv_bfloat16 g_xh[MTOT * DMODEL];
__device__ __nv_bfloat16 g_xl[MTOT * DMODEL];
__device__ __nv_bfloat16 g_oh[MTOT * DMODEL];
__device__ __nv_bfloat16 g_ol[MTOT * DMODEL];
__device__ __nv_bfloat16 g_w1h[3 * DMODEL * DMODEL];
__device__ __nv_bfloat16 g_w1l[3 * DMODEL * DMODEL];
__device__ __nv_bfloat16 g_w2h[DMODEL * DMODEL];
__device__ __nv_bfloat16 g_w2l[DMODEL * DMODEL];

// bf16 hi/lo Q/K/V for attention (written by qkv GEMM epilogue)
__device__ __nv_bfloat16 g_qh[BH * SEQ * DHEAD];     // [bh][n][d], pre-scaled
__device__ __nv_bfloat16 g_ql[BH * SEQ * DHEAD];
__device__ __nv_bfloat16 g_kh[BH * SEQ * DHEAD];     // [bh][n][d]
__device__ __nv_bfloat16 g_kl[BH * SEQ * DHEAD];
__device__ __nv_bfloat16 g_vth[BH * DHEAD * SEQ];    // [bh][d][n]  (transposed)
__device__ __nv_bfloat16 g_vtl[BH * DHEAD * SEQ];

// ---------------------------------------------------------------------------
// helpers
// ---------------------------------------------------------------------------
__device__ __forceinline__ uint32_t smem_u32(const void* p) {
    uint32_t a;
    asm("{ .reg .u64 t; cvta.to.shared.u64 t, %1; cvt.u32.u64 %0, t; }"
        : "=r"(a) : "l"(p));
    return a;
}

__device__ __forceinline__ void ldsm_x4(uint32_t* r, uint32_t addr) {
    asm volatile("ldmatrix.sync.aligned.m8n8.x4.shared.b16 {%0,%1,%2,%3}, [%4];"
                 : "=r"(r[0]), "=r"(r[1]), "=r"(r[2]), "=r"(r[3]) : "r"(addr));
}

__device__ __forceinline__ void mma_bf16(float* d, const uint32_t* a,
                                         uint32_t b0, uint32_t b1) {
    asm volatile(
        "mma.sync.aligned.m16n8k16.row.col.f32.bf16.bf16.f32 "
        "{%0,%1,%2,%3}, {%4,%5,%6,%7}, {%8,%9}, {%0,%1,%2,%3};"
        : "+f"(d[0]), "+f"(d[1]), "+f"(d[2]), "+f"(d[3])
        : "r"(a[0]), "r"(a[1]), "r"(a[2]), "r"(a[3]), "r"(b0), "r"(b1));
}

__device__ __forceinline__ void split1(float v, __nv_bfloat16& h, __nv_bfloat16& l) {
    h = __float2bfloat16(v);
    l = __float2bfloat16(v - __bfloat162float(h));
}

__device__ __forceinline__ void split2(float a, float b, uint32_t& h, uint32_t& l) {
    __nv_bfloat162 hh;
    hh.x = __float2bfloat16(a);
    hh.y = __float2bfloat16(b);
    float la = a - __bfloat162float(hh.x);
    float lb = b - __bfloat162float(hh.y);
    __nv_bfloat162 ll;
    ll.x = __float2bfloat16(la);
    ll.y = __float2bfloat16(lb);
    h = *(uint32_t*)&hh;
    l = *(uint32_t*)&ll;
}

__device__ __forceinline__ void cp16(uint32_t s, const void* g) {
    asm volatile("cp.async.cg.shared.global [%0], [%1], 16;" :: "r"(s), "l"(g));
}

// ---------------------------------------------------------------------------
// Convert kernels
// ---------------------------------------------------------------------------
__global__ __launch_bounds__(256) void conv_split(const float* __restrict__ in,
                                                  __nv_bfloat16* __restrict__ hi,
                                                  __nv_bfloat16* __restrict__ lo) {
    size_t i4 = (size_t)blockIdx.x * 256 + threadIdx.x;
    float4 v = ((const float4*)in)[i4];
    uint32_t h01, l01, h23, l23;
    split2(v.x, v.y, h01, l01);
    split2(v.z, v.w, h23, l23);
    ((uint2*)hi)[i4] = make_uint2(h01, h23);
    ((uint2*)lo)[i4] = make_uint2(l01, l23);
}

__global__ __launch_bounds__(256) void conv_wT(const float* __restrict__ W,
                                               __nv_bfloat16* __restrict__ Th,
                                               __nv_bfloat16* __restrict__ Tl,
                                               int N) {
    __shared__ float tile[32][33];
    const int tx = threadIdx.x, ty = threadIdx.y;
    const int n = blockIdx.x * 32 + tx;
#pragma unroll
    for (int j = 0; j < 32; j += 8) {
        int k = blockIdx.y * 32 + ty + j;
        tile[ty + j][tx] = W[(size_t)k * N + n];
    }
    __syncthreads();
    const int k = blockIdx.y * 32 + tx;
#pragma unroll
    for (int j = 0; j < 32; j += 8) {
        int n2 = blockIdx.x * 32 + ty + j;
        float v = tile[tx][ty + j];
        __nv_bfloat16 h, l;
        split1(v, h, l);
        Th[(size_t)n2 * DMODEL + k] = h;
        Tl[(size_t)n2 * DMODEL + k] = l;
    }
}

// ---------------------------------------------------------------------------
// HMMA GEMM (R8 pipeline): cp.async double-buffered, pre-converted operands.
// SCATTER=1: write bf16 hi/lo Q(scaled)/K/V^T for attention.
// SCATTER=0: out = result fp32.
// ---------------------------------------------------------------------------
#define BKE    64
#define ROWB   144
#define TILEB  (128 * ROWB)
#define STAGEB (4 * TILEB)
#define SMEM_TOTAL (2 * STAGEB)        // 147456 B
#define NCHUNK (DMODEL / BKE)          // 16

template <int SCATTER>
__global__ __launch_bounds__(256) void gemm_mma(const __nv_bfloat16* __restrict__ Ah,
                                                const __nv_bfloat16* __restrict__ Al,
                                                const __nv_bfloat16* __restrict__ Bh,
                                                const __nv_bfloat16* __restrict__ Bl,
                                                const float* __restrict__ bias,
                                                float* __restrict__ out) {
    extern __shared__ char smem[];
    const uint32_t sb = smem_u32(smem);

    const int tid  = threadIdx.x;
    const int warp = tid >> 5;
    const int lane = tid & 31;
    const int wm   = warp & 3;
    const int wn   = warp >> 2;
    const int n0   = blockIdx.x * 128;
    const int m0   = blockIdx.y * 128;

    float acc[2][8][4];
#pragma unroll
    for (int i = 0; i < 2; i++)
#pragma unroll
        for (int j = 0; j < 8; j++)
#pragma unroll
            for (int r = 0; r < 4; r++) acc[i][j][r] = 0.f;

    const __nv_bfloat16* base0 = Ah + (size_t)m0 * DMODEL;
    const __nv_bfloat16* base1 = Al + (size_t)m0 * DMODEL;
    const __nv_bfloat16* base2 = Bh + (size_t)n0 * DMODEL;
    const __nv_bfloat16* base3 = Bl + (size_t)n0 * DMODEL;

    const int cr = tid >> 3;
    const int cc = tid & 7;

    auto issue = [&](int s, int b) {
        const int k0 = s * BKE;
        const uint32_t dst = sb + b * STAGEB;
#pragma unroll
        for (int it = 0; it < 16; it++) {
            const int tile = it >> 2;
            const int r    = (it & 3) * 32 + cr;
            const __nv_bfloat16* src;
            if (tile == 0)      src = base0 + (size_t)r * DMODEL + k0 + cc * 8;
            else if (tile == 1) src = base1 + (size_t)r * DMODEL + k0 + cc * 8;
            else if (tile == 2) src = base2 + (size_t)r * DMODEL + k0 + cc * 8;
            else                src = base3 + (size_t)r * DMODEL + k0 + cc * 8;
            cp16(dst + tile * TILEB + r * ROWB + cc * 16, src);
        }
        asm volatile("cp.async.commit_group;");
    };

    issue(0, 0);
    issue(1, 1);

    const int lrow  = lane & 15;
    const int lcol8 = (lane >> 4) * 8;

    for (int s = 0; s < NCHUNK; s++) {
        if (s < NCHUNK - 1)
            asm volatile("cp.async.wait_group 1;" ::: "memory");
        else
            asm volatile("cp.async.wait_group 0;" ::: "memory");
        __syncthreads();

        const uint32_t buf = sb + (s & 1) * STAGEB;
        const uint32_t bAh = buf;
        const uint32_t bAl = buf + TILEB;
        const uint32_t bBh = buf + 2 * TILEB;
        const uint32_t bBl = buf + 3 * TILEB;

#pragma unroll
        for (int ks = 0; ks < 4; ks++) {
            const int kkb = (ks * 16 + lcol8) * 2;
            uint32_t a_hi[2][4], a_lo[2][4], b_cur[4][4];
#pragma unroll
            for (int mf = 0; mf < 2; mf++) {
                int r = wm * 32 + mf * 16 + lrow;
                ldsm_x4(a_hi[mf], bAh + r * ROWB + kkb);
                ldsm_x4(a_lo[mf], bAl + r * ROWB + kkb);
            }
#pragma unroll
            for (int g = 0; g < 4; g++) {
                int r = wn * 64 + g * 16 + lrow;
                ldsm_x4(b_cur[g], bBh + r * ROWB + kkb);
            }
#pragma unroll
            for (int mf = 0; mf < 2; mf++)
#pragma unroll
                for (int j = 0; j < 8; j++) {
                    int g = j >> 1, w = j & 1;
                    mma_bf16(acc[mf][j], a_hi[mf], b_cur[g][w], b_cur[g][w + 2]);
                    mma_bf16(acc[mf][j], a_lo[mf], b_cur[g][w], b_cur[g][w + 2]);
                }
#pragma unroll
            for (int g = 0; g < 4; g++) {
                int r = wn * 64 + g * 16 + lrow;
                ldsm_x4(b_cur[g], bBl + r * ROWB + kkb);
            }
#pragma unroll
            for (int mf = 0; mf < 2; mf++)
#pragma unroll
                for (int j = 0; j < 8; j++) {
                    int g = j >> 1, w = j & 1;
                    mma_bf16(acc[mf][j], a_hi[mf], b_cur[g][w], b_cur[g][w + 2]);
                }
        }
        __syncthreads();
        if (s + 2 < NCHUNK) issue(s + 2, s & 1);
    }

    const int gid = lane >> 2;
    const int tig = lane & 3;
#pragma unroll
    for (int mf = 0; mf < 2; mf++) {
#pragma unroll
        for (int j = 0; j < 8; j++) {
#pragma unroll
            for (int r = 0; r < 4; r++) {
                int m   = m0 + wm * 32 + mf * 16 + gid + ((r >> 1) * 8);
                int col = n0 + wn * 64 + j * 8 + tig * 2 + (r & 1);
                float v = acc[mf][j][r] + bias[col];
                if (SCATTER) {
                    int bi = m >> 11;
                    int ni = m & (SEQ - 1);
                    int which = col >> 10;
                    int rem   = col & 1023;
                    int hd    = rem >> 6;
                    int dd    = rem & 63;
                    int bh    = bi * NHEAD + hd;
                    __nv_bfloat16 h, l;
                    if (which == 0) {
                        split1(v * 0.125f, h, l);
                        size_t idx = ((size_t)bh * SEQ + ni) * DHEAD + dd;
                        g_qh[idx] = h; g_ql[idx] = l;
                    } else if (which == 1) {
                        split1(v, h, l);
                        size_t idx = ((size_t)bh * SEQ + ni) * DHEAD + dd;
                        g_kh[idx] = h; g_kl[idx] = l;
                    } else {
                        split1(v, h, l);
                        size_t idx = ((size_t)bh * DHEAD + dd) * SEQ + ni;
                        g_vth[idx] = h; g_vtl[idx] = l;
                    }
                } else {
                    out[(size_t)m * DMODEL + col] = v;
                }
            }
        }
    }
}

// ---------------------------------------------------------------------------
// HMMA flash attention (causal). CTA = 64 query rows of one (b,h).
// 128 threads / 4 warps; warp w owns rows [w*16, w*16+16).
// K blocks of 64 keys; S via 3-pass hi/lo MMA -> SMEM fp32 -> scalar online
// softmax -> P hi/lo -> 3-pass PV MMA into register O fragments.
// ---------------------------------------------------------------------------
#define AT_ROWB 144
#define AT_TILE (64 * AT_ROWB)                         // 9216 B
#define AT_SSTR 68                                     // S row stride (floats)
#define AT_SMEM (8 * AT_TILE + 64 * AT_SSTR * 4)       // 91136 B

__global__ __launch_bounds__(128) void attn_mma() {
    extern __shared__ char smem[];
    __shared__ float mrun[64], lrun[64], alph[64];
    const uint32_t sb  = smem_u32(smem);
    const uint32_t sQh = sb,               sQl = sb + AT_TILE;
    const uint32_t sKh = sb + 2 * AT_TILE, sKl = sb + 3 * AT_TILE;
    const uint32_t sVh = sb + 4 * AT_TILE, sVl = sb + 5 * AT_TILE;
    const uint32_t sPh = sb + 6 * AT_TILE, sPl = sb + 7 * AT_TILE;
    float* S = (float*)(smem + 8 * AT_TILE);

    const int qb   = blockIdx.x;
    const int bh   = blockIdx.y;
    const int tid  = threadIdx.x;
    const int warp = tid >> 5;
    const int lane = tid & 31;
    const int lrow  = lane & 15;
    const int lcol8 = (lane >> 4) * 8;
    const int gid = lane >> 2;
    const int tig = lane & 3;

    // ---- load Q hi/lo (64 x 128B per tile) ----
    {
        const __nv_bfloat16* qh = g_qh + ((size_t)bh * SEQ + qb * 64) * DHEAD;
        const __nv_bfloat16* ql = g_ql + ((size_t)bh * SEQ + qb * 64) * DHEAD;
        for (int i = tid; i < 512; i += 128) {
            int r = i >> 3, c = i & 7;
            cp16(sQh + r * AT_ROWB + c * 16, qh + (size_t)r * DHEAD + c * 8);
            cp16(sQl + r * AT_ROWB + c * 16, ql + (size_t)r * DHEAD + c * 8);
        }
        asm volatile("cp.async.commit_group;");
    }

    if (tid < 64) { mrun[tid] = -1e30f; lrun[tid] = 0.f; }

    float o[8][4];
#pragma unroll
    for (int j = 0; j < 8; j++)
#pragma unroll
        for (int r = 0; r < 4; r++) o[j][r] = 0.f;

    for (int kb = 0; kb <= qb; kb++) {
        // ---- load K hi/lo + V^T hi/lo for this 64-key block ----
        {
            const __nv_bfloat16* kh = g_kh + ((size_t)bh * SEQ + kb * 64) * DHEAD;
            const __nv_bfloat16* kl = g_kl + ((size_t)bh * SEQ + kb * 64) * DHEAD;
            const __nv_bfloat16* vh = g_vth + (size_t)bh * DHEAD * SEQ + kb * 64;
            const __nv_bfloat16* vl = g_vtl + (size_t)bh * DHEAD * SEQ + kb * 64;
            for (int i = tid; i < 512; i += 128) {
                int r = i >> 3, c = i & 7;
                cp16(sKh + r * AT_ROWB + c * 16, kh + (size_t)r * DHEAD + c * 8);
                cp16(sKl + r * AT_ROWB + c * 16, kl + (size_t)r * DHEAD + c * 8);
                cp16(sVh + r * AT_ROWB + c * 16, vh + (size_t)r * SEQ + c * 8);
                cp16(sVl + r * AT_ROWB + c * 16, vl + (size_t)r * SEQ + c * 8);
            }
            asm volatile("cp.async.commit_group;");
            asm volatile("cp.async.wait_group 0;" ::: "memory");
        }
        __syncthreads();

        // ---- S = Q K^T (3-pass hi/lo) ----
        float sfr[8][4];
#pragma unroll
        for (int j = 0; j < 8; j++)
#pragma unroll
            for (int r = 0; r < 4; r++) sfr[j][r] = 0.f;

#pragma unroll
        for (int ks = 0; ks < 4; ks++) {
            const int kkb = (ks * 16 + lcol8) * 2;
            uint32_t a_hi[4], a_lo[4], b_cur[4][4];
            int ar = warp * 16 + lrow;
            ldsm_x4(a_hi, sQh + ar * AT_ROWB + kkb);
            ldsm_x4(a_lo, sQl + ar * AT_ROWB + kkb);
#pragma unroll
            for (int g = 0; g < 4; g++)
                ldsm_x4(b_cur[g], sKh + (g * 16 + lrow) * AT_ROWB + kkb);
#pragma unroll
            for (int j = 0; j < 8; j++) {
                int g = j >> 1, w = j & 1;
                mma_bf16(sfr[j], a_hi, b_cur[g][w], b_cur[g][w + 2]);
                mma_bf16(sfr[j], a_lo, b_cur[g][w], b_cur[g][w + 2]);
            }
#pragma unroll
            for (int g = 0; g < 4; g++)
                ldsm_x4(b_cur[g], sKl + (g * 16 + lrow) * AT_ROWB + kkb);
#pragma unroll
            for (int j = 0; j < 8; j++) {
                int g = j >> 1, w = j & 1;
                mma_bf16(sfr[j], a_hi, b_cur[g][w], b_cur[g][w + 2]);
            }
        }
        // store S fragments
#pragma unroll
        for (int j = 0; j < 8; j++)
#pragma unroll
            for (int r = 0; r < 4; r++) {
                int row = warp * 16 + gid + (r >> 1) * 8;
                int col = j * 8 + tig * 2 + (r & 1);
                S[row * AT_SSTR + col] = sfr[j][r];
            }
        __syncthreads();

        // ---- scalar online softmax: 2 threads per row ----
        {
            const int row   = tid >> 1;
            const int half  = tid & 1;
            const int qglob = qb * 64 + row;
            const int kbase = kb * 64 + half * 32;
            const float* Sr = S + row * AT_SSTR + half * 32;
            float mx = -1e30f;
#pragma unroll
            for (int i = 0; i < 32; i++) {
                float s = (kbase + i <= qglob) ? Sr[i] : -1e30f;
                mx = fmaxf(mx, s);
            }
            mx = fmaxf(mx, __shfl_xor_sync(0xffffffffu, mx, 1));
            float mold = mrun[row];
            float mnew = fmaxf(mold, mx);
            float al   = __expf(mold - mnew);
            __nv_bfloat16* Php = (__nv_bfloat16*)(smem + 6 * AT_TILE + row * AT_ROWB) + half * 32;
            __nv_bfloat16* Plp = (__nv_bfloat16*)(smem + 7 * AT_TILE + row * AT_ROWB) + half * 32;
            float sum = 0.f;
#pragma unroll
            for (int i = 0; i < 32; i++) {
                float p = (kbase + i <= qglob) ? __expf(Sr[i] - mnew) : 0.f;
                sum += p;
                __nv_bfloat16 h, l;
                split1(p, h, l);
                Php[i] = h; Plp[i] = l;
            }
            sum += __shfl_xor_sync(0xffffffffu, sum, 1);
            if (half == 0) {
                lrun[row] = lrun[row] * al + sum;
                mrun[row] = mnew;
                alph[row] = al;
            }
        }
        __syncthreads();

        // ---- rescale O fragments ----
        {
            float a0 = alph[warp * 16 + gid];
            float a1 = alph[warp * 16 + gid + 8];
#pragma unroll
            for (int j = 0; j < 8; j++) {
                o[j][0] *= a0; o[j][1] *= a0;
                o[j][2] *= a1; o[j][3] *= a1;
            }
        }

        // ---- O += P V (3-pass hi/lo) ----
#pragma unroll
        for (int ks = 0; ks < 4; ks++) {
            const int kkb = (ks * 16 + lcol8) * 2;
            uint32_t p_hi[4], p_lo[4], b_cur[4][4];
            int ar = warp * 16 + lrow;
            ldsm_x4(p_hi, sPh + ar * AT_ROWB + kkb);
            ldsm_x4(p_lo, sPl + ar * AT_ROWB + kkb);
#pragma unroll
            for (int g = 0; g < 4; g++)
                ldsm_x4(b_cur[g], sVh + (g * 16 + lrow) * AT_ROWB + kkb);
#pragma unroll
            for (int j = 0; j < 8; j++) {
                int g = j >> 1, w = j & 1;
                mma_bf16(o[j], p_hi, b_cur[g][w], b_cur[g][w + 2]);
                mma_bf16(o[j], p_lo, b_cur[g][w], b_cur[g][w + 2]);
            }
#pragma unroll
            for (int g = 0; g < 4; g++)
                ldsm_x4(b_cur[g], sVl + (g * 16 + lrow) * AT_ROWB + kkb);
#pragma unroll
            for (int j = 0; j < 8; j++) {
                int g = j >> 1, w = j & 1;
                mma_bf16(o[j], p_hi, b_cur[g][w], b_cur[g][w + 2]);
            }
        }
        __syncthreads();   // protect SMEM before next block's loads
    }

    // ---- finalize: O /= l, write to g_o ----
    {
        float i0 = 1.f / lrun[warp * 16 + gid];
        float i1 = 1.f / lrun[warp * 16 + gid + 8];
        const int bi = bh >> 4;
        const int hd = bh & 15;
#pragma unroll
        for (int j = 0; j < 8; j++)
#pragma unroll
            for (int r = 0; r < 4; r++) {
                int row = qb * 64 + warp * 16 + gid + (r >> 1) * 8;
                int col = j * 8 + tig * 2 + (r & 1);
                float val = o[j][r] * ((r < 2) ? i0 : i1);
                g_o[((size_t)(bi * SEQ + row)) * DMODEL + hd * DHEAD + col] = val;
            }
    }
}

// ---------------------------------------------------------------------------
extern "C" void kernel_launch(void* const* d_in, const int* in_sizes, int n_in,
                              void* d_out, int out_size) {
    const float* x     = (const float*)d_in[0];
    const float* w_qkv = (const float*)d_in[1];
    const float* b_qkv = (const float*)d_in[2];
    const float* w_out = (const float*)d_in[3];
    const float* b_out = (const float*)d_in[4];
    float* out = (float*)d_out;

    __nv_bfloat16 *xh, *xl, *oh, *ol, *w1h, *w1l, *w2h, *w2l;
    float* o;
    cudaGetSymbolAddress((void**)&xh, g_xh);
    cudaGetSymbolAddress((void**)&xl, g_xl);
    cudaGetSymbolAddress((void**)&oh, g_oh);
    cudaGetSymbolAddress((void**)&ol, g_ol);
    cudaGetSymbolAddress((void**)&w1h, g_w1h);
    cudaGetSymbolAddress((void**)&w1l, g_w1l);
    cudaGetSymbolAddress((void**)&w2h, g_w2h);
    cudaGetSymbolAddress((void**)&w2l, g_w2l);
    cudaGetSymbolAddress((void**)&o, g_o);

    cudaFuncSetAttribute(gemm_mma<1>, cudaFuncAttributeMaxDynamicSharedMemorySize, SMEM_TOTAL);
    cudaFuncSetAttribute(gemm_mma<0>, cudaFuncAttributeMaxDynamicSharedMemorySize, SMEM_TOTAL);
    cudaFuncSetAttribute(attn_mma,    cudaFuncAttributeMaxDynamicSharedMemorySize, AT_SMEM);

    conv_split<<<MTOT * DMODEL / 4 / 256, 256>>>(x, xh, xl);
    conv_wT<<<dim3(3 * DMODEL / 32, DMODEL / 32), dim3(32, 8)>>>(w_qkv, w1h, w1l, 3 * DMODEL);
    conv_wT<<<dim3(DMODEL / 32, DMODEL / 32), dim3(32, 8)>>>(w_out, w2h, w2l, DMODEL);

    gemm_mma<1><<<dim3(3 * DMODEL / 128, MTOT / 128), 256, SMEM_TOTAL>>>(
        xh, xl, w1h, w1l, b_qkv, nullptr);

    attn_mma<<<dim3(SEQ / 64, BH), 128, AT_SMEM>>>();

    conv_split<<<MTOT * DMODEL / 4 / 256, 256>>>(o, oh, ol);

    gemm_mma<0><<<dim3(DMODEL / 128, MTOT / 128), 256, SMEM_TOTAL>>>(
        oh, ol, w2h, w2l, b_out, out);
}